// round 12
// baseline (speedup 1.0000x reference)
#include <cuda_runtime.h>

// Fused JPEG round-trip, high-occupancy layout: 768-thread CTA over a 256x8
// tile. One thread per (channel, block, row) for the transform phases (8
// scalar floats each); color phases run on 512 quad-threads. Transposes via
// conflict-free smem scatter (pitch 260). All math scalar.
// Input : d_in[0] = float32 [1,3,2048,2048]; Output: float32 [1,3*2048*2048]

#define IMG_W  2048
#define IMG_H  2048
#define PLANE  (IMG_W * IMG_H)
#define PITCH  260          // floats; 260%32==4 and 65%8==1 -> conflict-free

#define C1 0.4903926402f
#define C2 0.4619397663f
#define C3 0.4157348062f
#define C4 0.3535533906f
#define C5 0.2777851165f
#define C6 0.1913417162f
#define C7 0.0975451610f

__constant__ float cQf[128] = {
    16,11,10,16,24,40,51,61,  12,12,14,19,26,58,60,55,
    14,13,16,24,40,57,69,56,  14,17,22,29,51,87,80,62,
    18,22,37,56,68,109,103,77, 24,35,55,64,81,104,113,92,
    49,64,78,87,103,121,120,101, 72,92,95,98,112,100,103,99,
    17,18,24,47,99,99,99,99,  18,21,26,66,99,99,99,99,
    24,26,56,99,99,99,99,99,  47,66,99,99,99,99,99,99,
    99,99,99,99,99,99,99,99,  99,99,99,99,99,99,99,99,
    99,99,99,99,99,99,99,99,  99,99,99,99,99,99,99,99 };
__constant__ float cRQf[128] = {
    1.f/16,1.f/11,1.f/10,1.f/16,1.f/24,1.f/40,1.f/51,1.f/61,
    1.f/12,1.f/12,1.f/14,1.f/19,1.f/26,1.f/58,1.f/60,1.f/55,
    1.f/14,1.f/13,1.f/16,1.f/24,1.f/40,1.f/57,1.f/69,1.f/56,
    1.f/14,1.f/17,1.f/22,1.f/29,1.f/51,1.f/87,1.f/80,1.f/62,
    1.f/18,1.f/22,1.f/37,1.f/56,1.f/68,1.f/109,1.f/103,1.f/77,
    1.f/24,1.f/35,1.f/55,1.f/64,1.f/81,1.f/104,1.f/113,1.f/92,
    1.f/49,1.f/64,1.f/78,1.f/87,1.f/103,1.f/121,1.f/120,1.f/101,
    1.f/72,1.f/92,1.f/95,1.f/98,1.f/112,1.f/100,1.f/103,1.f/99,
    1.f/17,1.f/18,1.f/24,1.f/47,1.f/99,1.f/99,1.f/99,1.f/99,
    1.f/18,1.f/21,1.f/26,1.f/66,1.f/99,1.f/99,1.f/99,1.f/99,
    1.f/24,1.f/26,1.f/56,1.f/99,1.f/99,1.f/99,1.f/99,1.f/99,
    1.f/47,1.f/66,1.f/99,1.f/99,1.f/99,1.f/99,1.f/99,1.f/99,
    1.f/99,1.f/99,1.f/99,1.f/99,1.f/99,1.f/99,1.f/99,1.f/99,
    1.f/99,1.f/99,1.f/99,1.f/99,1.f/99,1.f/99,1.f/99,1.f/99,
    1.f/99,1.f/99,1.f/99,1.f/99,1.f/99,1.f/99,1.f/99,1.f/99,
    1.f/99,1.f/99,1.f/99,1.f/99,1.f/99,1.f/99,1.f/99,1.f/99 };

// Folded inverse-color + normalization (validated R5-R11)
#define NC_A0 0.0158730159f
#define NC_B0 (-1.93476190e-8f)
#define NC_C0 0.0222539619f
#define NC_K0 (-4.8373935f)
#define NC_A1 0.0161030596f
#define NC_B1 (-0.0055416377f)
#define NC_C1 (-0.0114997768f)
#define NC_K1 0.2006247f
#define NC_A2 0.0149925037f
#define NC_B2 0.0265667181f
#define NC_C2 6.09145427e-9f
#define NC_K2 (-5.1081869f)

__device__ __forceinline__ void fdct8(float v[8]) {
    float e0=v[0]+v[7], e1=v[1]+v[6], e2=v[2]+v[5], e3=v[3]+v[4];
    float o0=v[0]-v[7], o1=v[1]-v[6], o2=v[2]-v[5], o3=v[3]-v[4];
    float s03=e0+e3, s12=e1+e2, d03=e0-e3, d12=e1-e2;
    v[0]=C4*(s03+s12);
    v[4]=C4*(s03-s12);
    v[2]=fmaf(C2,d03, C6*d12);
    v[6]=fmaf(C6,d03,-C2*d12);
    v[1]=fmaf(C1,o0,fmaf( C3,o1,fmaf( C5,o2, C7*o3)));
    v[3]=fmaf(C3,o0,fmaf(-C7,o1,fmaf(-C1,o2,-C5*o3)));
    v[5]=fmaf(C5,o0,fmaf(-C1,o1,fmaf( C7,o2, C3*o3)));
    v[7]=fmaf(C7,o0,fmaf(-C5,o1,fmaf( C3,o2,-C1*o3)));
}
__device__ __forceinline__ void idct8(float v[8]) {
    float sp=C4*(v[0]+v[4]), sm=C4*(v[0]-v[4]);
    float t1=fmaf(C2,v[2], C6*v[6]);
    float t2=fmaf(C6,v[2],-C2*v[6]);
    float E0=sp+t1, E1=sm+t2, E2=sm-t2, E3=sp-t1;
    float O0=fmaf(C1,v[1],fmaf( C3,v[3],fmaf( C5,v[5], C7*v[7])));
    float O1=fmaf(C3,v[1],fmaf(-C7,v[3],fmaf(-C1,v[5],-C5*v[7])));
    float O2=fmaf(C5,v[1],fmaf(-C1,v[3],fmaf( C7,v[5], C3*v[7])));
    float O3=fmaf(C7,v[1],fmaf(-C5,v[3],fmaf( C3,v[5],-C1*v[7])));
    v[0]=E0+O0; v[7]=E0-O0;
    v[1]=E1+O1; v[6]=E1-O1;
    v[2]=E2+O2; v[5]=E2-O2;
    v[3]=E3+O3; v[4]=E3-O3;
}

__global__ __launch_bounds__(768, 2)
void jpeg_roundtrip_kernel(const float* __restrict__ in, float* __restrict__ out)
{
    // YUV tile: 3 channels x 8 rows x PITCH floats = 24960 B
    __shared__ __align__(16) float yuv[3][8 * PITCH];
    __shared__ float qt[256];   // interleaved (q, rq), [ch][i][r]

    const int tid = threadIdx.x;

    {   // build interleaved quant table
        if (tid < 256) {
            int w  = tid & 1, rr = (tid >> 1) & 7, ii = (tid >> 4) & 7, ch = tid >> 7;
            int si = ch * 64 + ii * 8 + rr;
            qt[tid] = w ? cRQf[si] : cQf[si];
        }
    }

    const int x0 = blockIdx.x * 256;
    const int y0 = blockIdx.y * 8;

    // ================= phase A: load RGB, forward color -> smem =================
    if (tid < 512) {
        int row = tid >> 6;             // 8 rows, 64 quads per row
        int c4  = (tid & 63) << 2;
        int gb  = (y0 + row) * IMG_W + x0 + c4;
        float4 R = *(const float4*)(in + gb);
        float4 G = *(const float4*)(in + gb + PLANE);
        float4 B = *(const float4*)(in + gb + 2*PLANE);
        float4 Y, U, V;
        #pragma unroll
        for (int k = 0; k < 4; ++k) {
            float r = ((float*)&R)[k], g = ((float*)&G)[k], b = ((float*)&B)[k];
            ((float*)&Y)[k] = 0.299f*r + 0.587f*g + 0.114f*b;
            ((float*)&U)[k] = fmaf(-0.168736f, r, fmaf(-0.331264f, g, fmaf(0.5f, b, 128.0f)));
            ((float*)&V)[k] = fmaf(0.5f, r, fmaf(-0.418688f, g, fmaf(-0.081312f, b, 128.0f)));
        }
        int sa = row * PITCH + c4;
        *(float4*)(&yuv[0][sa]) = Y;
        *(float4*)(&yuv[1][sa]) = U;
        *(float4*)(&yuv[2][sa]) = V;
    }
    __syncthreads();

    // ================= phase B: per (channel, block, row) transforms =================
    {
        const int ch  = tid >> 8;        // 0..2
        const int idx = tid & 255;
        const int b   = idx >> 3;        // block 0..31
        const int r   = idx & 7;         // row within block
        float* base = yuv[ch];
        const float* qte = qt + (ch > 0 ? 128 : 0);
        const int rowoff = r * PITCH + b * 8;

        float v[8];
        // read natural row
        {
            float4 lo = *(const float4*)(base + rowoff);
            float4 hi = *(const float4*)(base + rowoff + 4);
            v[0]=lo.x; v[1]=lo.y; v[2]=lo.z; v[3]=lo.w;
            v[4]=hi.x; v[5]=hi.y; v[6]=hi.z; v[7]=hi.w;
        }
        fdct8(v);
        __syncwarp();
        #pragma unroll
        for (int k = 0; k < 8; ++k) base[k * PITCH + b * 8 + r] = v[k];   // scatter = transpose
        __syncwarp();
        {
            float4 lo = *(const float4*)(base + rowoff);
            float4 hi = *(const float4*)(base + rowoff + 4);
            v[0]=lo.x; v[1]=lo.y; v[2]=lo.z; v[3]=lo.w;
            v[4]=hi.x; v[5]=hi.y; v[6]=hi.z; v[7]=hi.w;
        }
        fdct8(v);      // full DCT done; thread holds coeff [i][r] at index i
        #pragma unroll
        for (int i = 0; i < 8; ++i) {
            float2 qq = *(const float2*)(qte + i * 16 + r * 2);
            float sv = v[i];
            float d  = sv * qq.y;
            float rn = rintf(d);
            float e  = fmaf(-rn, qq.x, sv) * qq.y;
            v[i]     = fmaf(e*e, e, rn) * qq.x;
        }
        idct8(v);
        __syncwarp();
        #pragma unroll
        for (int k = 0; k < 8; ++k) base[k * PITCH + b * 8 + r] = v[k];   // transpose back
        __syncwarp();
        {
            float4 lo = *(const float4*)(base + rowoff);
            float4 hi = *(const float4*)(base + rowoff + 4);
            v[0]=lo.x; v[1]=lo.y; v[2]=lo.z; v[3]=lo.w;
            v[4]=hi.x; v[5]=hi.y; v[6]=hi.z; v[7]=hi.w;
        }
        idct8(v);
        __syncwarp();
        // write reconstructed natural row
        *(float4*)(base + rowoff)     = make_float4(v[0], v[1], v[2], v[3]);
        *(float4*)(base + rowoff + 4) = make_float4(v[4], v[5], v[6], v[7]);
    }
    __syncthreads();

    // ================= phase C: inverse color + normalize -> global =================
    if (tid < 512) {
        int row = tid >> 6;
        int c4  = (tid & 63) << 2;
        int sa  = row * PITCH + c4;
        float4 Y = *(const float4*)(&yuv[0][sa]);
        float4 U = *(const float4*)(&yuv[1][sa]);
        float4 V = *(const float4*)(&yuv[2][sa]);
        float4 Ro, Go, Bo;
        #pragma unroll
        for (int k = 0; k < 4; ++k) {
            float yv = ((float*)&Y)[k];
            float u  = ((float*)&U)[k];
            float vv = ((float*)&V)[k];
            ((float*)&Ro)[k] = fmaf(yv, NC_A0, fmaf(u, NC_B0, fmaf(vv, NC_C0, NC_K0)));
            ((float*)&Go)[k] = fmaf(yv, NC_A1, fmaf(u, NC_B1, fmaf(vv, NC_C1, NC_K1)));
            ((float*)&Bo)[k] = fmaf(yv, NC_A2, fmaf(u, NC_B2, fmaf(vv, NC_C2, NC_K2)));
        }
        int gb = (y0 + row) * IMG_W + x0 + c4;
        *(float4*)(out + gb)           = Ro;
        *(float4*)(out + gb + PLANE)   = Go;
        *(float4*)(out + gb + 2*PLANE) = Bo;
    }
}

extern "C" void kernel_launch(void* const* d_in, const int* in_sizes, int n_in,
                              void* d_out, int out_size)
{
    const float* in = (const float*)d_in[0];
    float* out = (float*)d_out;
    dim3 grid(IMG_W / 256, IMG_H / 8);
    jpeg_roundtrip_kernel<<<grid, 768>>>(in, out);
}

// round 13
// speedup vs baseline: 1.2352x; 1.2352x over previous
#include <cuda_runtime.h>
#include <cstring>

// Fused JPEG round-trip. Thread owns row r of TWO vertically adjacent 8x8
// blocks, processed as FOUR interleaved streams (Y_A, UV_A, Y_B, UV_B) to
// overlap fma-pipe and smem-pipe phases. Y scalar, U+V packed f32x2.
// Transposes via per-warp conflict-free smem; 4 barriers per thread total.
// Input : d_in[0] = float32 [1,3,2048,2048]; Output: float32 [1,3*2048*2048]

#define IMG_W  2048
#define IMG_H  2048
#define PLANE  (IMG_W * IMG_H)

#define C1 0.4903926402f
#define C2 0.4619397663f
#define C3 0.4157348062f
#define C4 0.3535533906f
#define C5 0.2777851165f
#define C6 0.1913417162f
#define C7 0.0975451610f

__constant__ float cQf[128] = {
    16,11,10,16,24,40,51,61,  12,12,14,19,26,58,60,55,
    14,13,16,24,40,57,69,56,  14,17,22,29,51,87,80,62,
    18,22,37,56,68,109,103,77, 24,35,55,64,81,104,113,92,
    49,64,78,87,103,121,120,101, 72,92,95,98,112,100,103,99,
    17,18,24,47,99,99,99,99,  18,21,26,66,99,99,99,99,
    24,26,56,99,99,99,99,99,  47,66,99,99,99,99,99,99,
    99,99,99,99,99,99,99,99,  99,99,99,99,99,99,99,99,
    99,99,99,99,99,99,99,99,  99,99,99,99,99,99,99,99 };
__constant__ float cRQf[128] = {
    1.f/16,1.f/11,1.f/10,1.f/16,1.f/24,1.f/40,1.f/51,1.f/61,
    1.f/12,1.f/12,1.f/14,1.f/19,1.f/26,1.f/58,1.f/60,1.f/55,
    1.f/14,1.f/13,1.f/16,1.f/24,1.f/40,1.f/57,1.f/69,1.f/56,
    1.f/14,1.f/17,1.f/22,1.f/29,1.f/51,1.f/87,1.f/80,1.f/62,
    1.f/18,1.f/22,1.f/37,1.f/56,1.f/68,1.f/109,1.f/103,1.f/77,
    1.f/24,1.f/35,1.f/55,1.f/64,1.f/81,1.f/104,1.f/113,1.f/92,
    1.f/49,1.f/64,1.f/78,1.f/87,1.f/103,1.f/121,1.f/120,1.f/101,
    1.f/72,1.f/92,1.f/95,1.f/98,1.f/112,1.f/100,1.f/103,1.f/99,
    1.f/17,1.f/18,1.f/24,1.f/47,1.f/99,1.f/99,1.f/99,1.f/99,
    1.f/18,1.f/21,1.f/26,1.f/66,1.f/99,1.f/99,1.f/99,1.f/99,
    1.f/24,1.f/26,1.f/56,1.f/99,1.f/99,1.f/99,1.f/99,1.f/99,
    1.f/47,1.f/66,1.f/99,1.f/99,1.f/99,1.f/99,1.f/99,1.f/99,
    1.f/99,1.f/99,1.f/99,1.f/99,1.f/99,1.f/99,1.f/99,1.f/99,
    1.f/99,1.f/99,1.f/99,1.f/99,1.f/99,1.f/99,1.f/99,1.f/99,
    1.f/99,1.f/99,1.f/99,1.f/99,1.f/99,1.f/99,1.f/99,1.f/99,
    1.f/99,1.f/99,1.f/99,1.f/99,1.f/99,1.f/99,1.f/99,1.f/99 };

#define NC_A0 0.0158730159f
#define NC_B0 (-1.93476190e-8f)
#define NC_C0 0.0222539619f
#define NC_K0 (-4.8373935f)
#define NC_A1 0.0161030596f
#define NC_B1 (-0.0055416377f)
#define NC_C1 (-0.0114997768f)
#define NC_K1 0.2006247f
#define NC_A2 0.0149925037f
#define NC_B2 0.0265667181f
#define NC_C2 6.09145427e-9f
#define NC_K2 (-5.1081869f)

typedef unsigned long long ull;

__device__ __forceinline__ ull pk(float lo, float hi) {
    float2 t = make_float2(lo, hi); ull r; memcpy(&r, &t, 8); return r;
}
__device__ __forceinline__ ull pk1(float x) { return pk(x, x); }
__device__ __forceinline__ float2 unpk(ull a) {
    float2 t; memcpy(&t, &a, 8); return t;
}
__device__ __forceinline__ ull padd(ull a, ull b) {
    ull r; asm("add.rn.f32x2 %0,%1,%2;" : "=l"(r) : "l"(a), "l"(b)); return r;
}
__device__ __forceinline__ ull pmul(ull a, ull b) {
    ull r; asm("mul.rn.f32x2 %0,%1,%2;" : "=l"(r) : "l"(a), "l"(b)); return r;
}
__device__ __forceinline__ ull pfma(ull a, ull b, ull c) {
    ull r; asm("fma.rn.f32x2 %0,%1,%2,%3;" : "=l"(r) : "l"(a), "l"(b), "l"(c)); return r;
}
__device__ __forceinline__ ull psub(ull a, ull b) { return pfma(b, pk1(-1.0f), a); }

__device__ __forceinline__ void fdct8(float v[8]) {
    float e0=v[0]+v[7], e1=v[1]+v[6], e2=v[2]+v[5], e3=v[3]+v[4];
    float o0=v[0]-v[7], o1=v[1]-v[6], o2=v[2]-v[5], o3=v[3]-v[4];
    float s03=e0+e3, s12=e1+e2, d03=e0-e3, d12=e1-e2;
    v[0]=C4*(s03+s12);
    v[4]=C4*(s03-s12);
    v[2]=fmaf(C2,d03, C6*d12);
    v[6]=fmaf(C6,d03,-C2*d12);
    v[1]=fmaf(C1,o0,fmaf( C3,o1,fmaf( C5,o2, C7*o3)));
    v[3]=fmaf(C3,o0,fmaf(-C7,o1,fmaf(-C1,o2,-C5*o3)));
    v[5]=fmaf(C5,o0,fmaf(-C1,o1,fmaf( C7,o2, C3*o3)));
    v[7]=fmaf(C7,o0,fmaf(-C5,o1,fmaf( C3,o2,-C1*o3)));
}
__device__ __forceinline__ void idct8(float v[8]) {
    float sp=C4*(v[0]+v[4]), sm=C4*(v[0]-v[4]);
    float t1=fmaf(C2,v[2], C6*v[6]);
    float t2=fmaf(C6,v[2],-C2*v[6]);
    float E0=sp+t1, E1=sm+t2, E2=sm-t2, E3=sp-t1;
    float O0=fmaf(C1,v[1],fmaf( C3,v[3],fmaf( C5,v[5], C7*v[7])));
    float O1=fmaf(C3,v[1],fmaf(-C7,v[3],fmaf(-C1,v[5],-C5*v[7])));
    float O2=fmaf(C5,v[1],fmaf(-C1,v[3],fmaf( C7,v[5], C3*v[7])));
    float O3=fmaf(C7,v[1],fmaf(-C5,v[3],fmaf( C3,v[5],-C1*v[7])));
    v[0]=E0+O0; v[7]=E0-O0;
    v[1]=E1+O1; v[6]=E1-O1;
    v[2]=E2+O2; v[5]=E2-O2;
    v[3]=E3+O3; v[4]=E3-O3;
}
__device__ __forceinline__ void fdct8p(ull v[8]) {
    ull e0=padd(v[0],v[7]), e1=padd(v[1],v[6]), e2=padd(v[2],v[5]), e3=padd(v[3],v[4]);
    ull o0=psub(v[0],v[7]), o1=psub(v[1],v[6]), o2=psub(v[2],v[5]), o3=psub(v[3],v[4]);
    ull s03=padd(e0,e3), s12=padd(e1,e2), d03=psub(e0,e3), d12=psub(e1,e2);
    v[0]=pmul(pk1(C4), padd(s03,s12));
    v[4]=pmul(pk1(C4), psub(s03,s12));
    v[2]=pfma(pk1(C2),d03, pmul(pk1( C6),d12));
    v[6]=pfma(pk1(C6),d03, pmul(pk1(-C2),d12));
    v[1]=pfma(pk1(C1),o0, pfma(pk1( C3),o1, pfma(pk1( C5),o2, pmul(pk1( C7),o3))));
    v[3]=pfma(pk1(C3),o0, pfma(pk1(-C7),o1, pfma(pk1(-C1),o2, pmul(pk1(-C5),o3))));
    v[5]=pfma(pk1(C5),o0, pfma(pk1(-C1),o1, pfma(pk1( C7),o2, pmul(pk1( C3),o3))));
    v[7]=pfma(pk1(C7),o0, pfma(pk1(-C5),o1, pfma(pk1( C3),o2, pmul(pk1(-C1),o3))));
}
__device__ __forceinline__ void idct8p(ull v[8]) {
    ull sp=pmul(pk1(C4), padd(v[0],v[4]));
    ull sm=pmul(pk1(C4), psub(v[0],v[4]));
    ull t1=pfma(pk1(C2),v[2], pmul(pk1( C6),v[6]));
    ull t2=pfma(pk1(C6),v[2], pmul(pk1(-C2),v[6]));
    ull E0=padd(sp,t1), E1=padd(sm,t2), E2=psub(sm,t2), E3=psub(sp,t1);
    ull O0=pfma(pk1(C1),v[1], pfma(pk1( C3),v[3], pfma(pk1( C5),v[5], pmul(pk1( C7),v[7]))));
    ull O1=pfma(pk1(C3),v[1], pfma(pk1(-C7),v[3], pfma(pk1(-C1),v[5], pmul(pk1(-C5),v[7]))));
    ull O2=pfma(pk1(C5),v[1], pfma(pk1(-C1),v[3], pfma(pk1( C7),v[5], pmul(pk1( C3),v[7]))));
    ull O3=pfma(pk1(C7),v[1], pfma(pk1(-C5),v[3], pfma(pk1( C3),v[5], pmul(pk1(-C1),v[7]))));
    v[0]=padd(E0,O0); v[7]=psub(E0,O0);
    v[1]=padd(E1,O1); v[6]=psub(E1,O1);
    v[2]=padd(E2,O2); v[5]=psub(E2,O2);
    v[3]=padd(E3,O3); v[4]=psub(E3,O3);
}

// conflict-free smem layouts (validated R8-R11)
#define RPY 12
#define GPY 104
#define RPU 10
#define GPU 84

__device__ __forceinline__ void writeY(const float vy[8], float* ybg, int r) {
    float* yw = ybg + RPY * r;
    *(float4*)(yw)     = make_float4(vy[0], vy[1], vy[2], vy[3]);
    *(float4*)(yw + 4) = make_float4(vy[4], vy[5], vy[6], vy[7]);
}
__device__ __forceinline__ void writeUV(const ull uv[8], ull* uvbg, int r) {
    ull* uw = uvbg + RPU * r;
    #pragma unroll
    for (int k = 0; k < 8; k += 2)
        *(ulonglong2*)(uw + k) = make_ulonglong2(uv[k], uv[k+1]);
}
__device__ __forceinline__ void readY(float vy[8], const float* ybg, int r) {
    #pragma unroll
    for (int k = 0; k < 8; ++k) vy[k] = ybg[RPY * k + r];
}
__device__ __forceinline__ void readUV(ull uv[8], const ull* uvbg, int r) {
    #pragma unroll
    for (int k = 0; k < 8; ++k) uv[k] = uvbg[RPU * k + r];
}

__global__ __launch_bounds__(128, 6)
void jpeg_roundtrip_kernel(const float* __restrict__ in, float* __restrict__ out)
{
    // per-tile buffers: Y (float) and UV (ull), 16 groups each
    __shared__ __align__(16) float ybA[16 * GPY], ybB[16 * GPY];   // 2 x 6656 B
    __shared__ __align__(16) ull  uvbA[16 * GPU], uvbB[16 * GPU];  // 2 x 10752 B
    __shared__ float qt[256];

    const int tid  = threadIdx.x;
    const int warp = tid >> 5;
    const int lane = tid & 31;
    const int r    = lane >> 2;
    const int g    = lane & 3;

    #pragma unroll
    for (int t = tid; t < 256; t += 128) {
        int w  = t & 1, rr = (t >> 1) & 7, ii = (t >> 4) & 7, ch = t >> 7;
        int si = ch * 64 + ii * 8 + rr;
        qt[t] = w ? cRQf[si] : cQf[si];
    }

    const int grp = warp * 4 + g;
    float* ygA  = ybA  + grp * GPY;
    float* ygB  = ybB  + grp * GPY;
    ull*   uvgA = uvbA + grp * GPU;
    ull*   uvgB = uvbB + grp * GPU;

    const int x0    = blockIdx.x * 128 + grp * 8;
    const int yA    = blockIdx.y * 16 + r;
    const int baseA = yA * IMG_W + x0;
    const int baseB = baseA + 8 * IMG_W;

    // ---- all 12 loads up front ----
    const float4 ARa = *(const float4*)(in + baseA);
    const float4 ARb = *(const float4*)(in + baseA + 4);
    const float4 AGa = *(const float4*)(in + baseA + PLANE);
    const float4 AGb = *(const float4*)(in + baseA + PLANE + 4);
    const float4 ABa = *(const float4*)(in + baseA + 2*PLANE);
    const float4 ABb = *(const float4*)(in + baseA + 2*PLANE + 4);
    const float4 BRa = *(const float4*)(in + baseB);
    const float4 BRb = *(const float4*)(in + baseB + 4);
    const float4 BGa = *(const float4*)(in + baseB + PLANE);
    const float4 BGb = *(const float4*)(in + baseB + PLANE + 4);
    const float4 BBa = *(const float4*)(in + baseB + 2*PLANE);
    const float4 BBb = *(const float4*)(in + baseB + 2*PLANE + 4);

    __syncthreads();   // quant table ready

    // ---- forward color, both tiles ----
    float YA[8], YB[8];
    ull   UVA[8], UVB[8];
    {
        float RA[8] = {ARa.x,ARa.y,ARa.z,ARa.w, ARb.x,ARb.y,ARb.z,ARb.w};
        float GA[8] = {AGa.x,AGa.y,AGa.z,AGa.w, AGb.x,AGb.y,AGb.z,AGb.w};
        float BA[8] = {ABa.x,ABa.y,ABa.z,ABa.w, ABb.x,ABb.y,ABb.z,ABb.w};
        float RB[8] = {BRa.x,BRa.y,BRa.z,BRa.w, BRb.x,BRb.y,BRb.z,BRb.w};
        float GB[8] = {BGa.x,BGa.y,BGa.z,BGa.w, BGb.x,BGb.y,BGb.z,BGb.w};
        float BBv[8]= {BBa.x,BBa.y,BBa.z,BBa.w, BBb.x,BBb.y,BBb.z,BBb.w};
        #pragma unroll
        for (int k = 0; k < 8; ++k) {
            YA[k] = 0.299f*RA[k] + 0.587f*GA[k] + 0.114f*BA[k];
            float ua = fmaf(-0.168736f, RA[k], fmaf(-0.331264f, GA[k], fmaf(0.5f, BA[k], 128.0f)));
            float va = fmaf(0.5f, RA[k], fmaf(-0.418688f, GA[k], fmaf(-0.081312f, BA[k], 128.0f)));
            UVA[k] = pk(ua, va);
            YB[k] = 0.299f*RB[k] + 0.587f*GB[k] + 0.114f*BBv[k];
            float ub = fmaf(-0.168736f, RB[k], fmaf(-0.331264f, GB[k], fmaf(0.5f, BBv[k], 128.0f)));
            float vb = fmaf(0.5f, RB[k], fmaf(-0.418688f, GB[k], fmaf(-0.081312f, BBv[k], 128.0f)));
            UVB[k] = pk(ub, vb);
        }
    }

    // ---- stage 1: row DCT (4 independent streams), then one write+read burst ----
    fdct8(YA); fdct8(YB); fdct8p(UVA); fdct8p(UVB);
    writeY(YA, ygA, r); writeY(YB, ygB, r);
    writeUV(UVA, uvgA, r); writeUV(UVB, uvgB, r);
    __syncwarp();
    readY(YA, ygA, r); readY(YB, ygB, r);
    readUV(UVA, uvgA, r); readUV(UVB, uvgB, r);
    __syncwarp();

    // ---- stage 2+3: column DCT, quant (shared qq loads), column IDCT ----
    fdct8(YA); fdct8(YB); fdct8p(UVA); fdct8p(UVB);
    #pragma unroll
    for (int i = 0; i < 8; ++i) {
        float2 qy = *(const float2*)(qt + i * 16 + r * 2);
        float2 qc = *(const float2*)(qt + 128 + i * 16 + r * 2);
        {   float sv = YA[i];
            float d  = sv * qy.y;
            float rn = rintf(d);
            float e  = fmaf(-rn, qy.x, sv) * qy.y;
            YA[i]    = fmaf(e*e, e, rn) * qy.x; }
        {   float sv = YB[i];
            float d  = sv * qy.y;
            float rn = rintf(d);
            float e  = fmaf(-rn, qy.x, sv) * qy.y;
            YB[i]    = fmaf(e*e, e, rn) * qy.x; }
        {   float2 s = unpk(UVA[i]);
            float d0 = s.x * qc.y, d1 = s.y * qc.y;
            float r0 = rintf(d0), r1 = rintf(d1);
            float e0 = fmaf(-r0, qc.x, s.x) * qc.y;
            float e1 = fmaf(-r1, qc.x, s.y) * qc.y;
            UVA[i] = pk(fmaf(e0*e0, e0, r0) * qc.x, fmaf(e1*e1, e1, r1) * qc.x); }
        {   float2 s = unpk(UVB[i]);
            float d0 = s.x * qc.y, d1 = s.y * qc.y;
            float r0 = rintf(d0), r1 = rintf(d1);
            float e0 = fmaf(-r0, qc.x, s.x) * qc.y;
            float e1 = fmaf(-r1, qc.x, s.y) * qc.y;
            UVB[i] = pk(fmaf(e0*e0, e0, r0) * qc.x, fmaf(e1*e1, e1, r1) * qc.x); }
    }
    idct8(YA); idct8(YB); idct8p(UVA); idct8p(UVB);
    writeY(YA, ygA, r); writeY(YB, ygB, r);
    writeUV(UVA, uvgA, r); writeUV(UVB, uvgB, r);
    __syncwarp();
    readY(YA, ygA, r); readY(YB, ygB, r);
    readUV(UVA, uvgA, r); readUV(UVB, uvgB, r);

    // ---- stage 4: row IDCT, 4 streams ----
    idct8(YA); idct8(YB); idct8p(UVA); idct8p(UVB);

    // ---- folded inverse color + normalize + store, both tiles ----
    #pragma unroll
    for (int h = 0; h < 2; ++h) {
        float4 RoA, GoA, BoA, RoB, GoB, BoB;
        #pragma unroll
        for (int k = 0; k < 4; ++k) {
            int c = h*4 + k;
            {   float yv = YA[c];
                float2 uvv = unpk(UVA[c]);
                ((float*)&RoA)[k] = fmaf(yv, NC_A0, fmaf(uvv.x, NC_B0, fmaf(uvv.y, NC_C0, NC_K0)));
                ((float*)&GoA)[k] = fmaf(yv, NC_A1, fmaf(uvv.x, NC_B1, fmaf(uvv.y, NC_C1, NC_K1)));
                ((float*)&BoA)[k] = fmaf(yv, NC_A2, fmaf(uvv.x, NC_B2, fmaf(uvv.y, NC_C2, NC_K2))); }
            {   float yv = YB[c];
                float2 uvv = unpk(UVB[c]);
                ((float*)&RoB)[k] = fmaf(yv, NC_A0, fmaf(uvv.x, NC_B0, fmaf(uvv.y, NC_C0, NC_K0)));
                ((float*)&GoB)[k] = fmaf(yv, NC_A1, fmaf(uvv.x, NC_B1, fmaf(uvv.y, NC_C1, NC_K1)));
                ((float*)&BoB)[k] = fmaf(yv, NC_A2, fmaf(uvv.x, NC_B2, fmaf(uvv.y, NC_C2, NC_K2))); }
        }
        *(float4*)(out + baseA + h*4)           = RoA;
        *(float4*)(out + baseA + PLANE + h*4)   = GoA;
        *(float4*)(out + baseA + 2*PLANE + h*4) = BoA;
        *(float4*)(out + baseB + h*4)           = RoB;
        *(float4*)(out + baseB + PLANE + h*4)   = GoB;
        *(float4*)(out + baseB + 2*PLANE + h*4) = BoB;
    }
}

extern "C" void kernel_launch(void* const* d_in, const int* in_sizes, int n_in,
                              void* d_out, int out_size)
{
    const float* in = (const float*)d_in[0];
    float* out = (float*)d_out;
    dim3 grid(IMG_W / 128, IMG_H / 16);
    jpeg_roundtrip_kernel<<<grid, 128>>>(in, out);
}

// round 14
// speedup vs baseline: 1.3148x; 1.0645x over previous
#include <cuda_runtime.h>
#include <cstring>

// Fused JPEG round-trip (R8 structure). Thread owns row r of ONE 8x8 block:
// Y scalar, U+V packed f32x2. Y transposes via warp SHUFFLE butterflies
// (off the LSU); UV transposes via conflict-free smem. launch_bounds(256,4).
// Input : d_in[0] = float32 [1,3,2048,2048]; Output: float32 [1,3*2048*2048]

#define IMG_W  2048
#define IMG_H  2048
#define PLANE  (IMG_W * IMG_H)

#define C1 0.4903926402f
#define C2 0.4619397663f
#define C3 0.4157348062f
#define C4 0.3535533906f
#define C5 0.2777851165f
#define C6 0.1913417162f
#define C7 0.0975451610f

__constant__ float cQf[128] = {
    16,11,10,16,24,40,51,61,  12,12,14,19,26,58,60,55,
    14,13,16,24,40,57,69,56,  14,17,22,29,51,87,80,62,
    18,22,37,56,68,109,103,77, 24,35,55,64,81,104,113,92,
    49,64,78,87,103,121,120,101, 72,92,95,98,112,100,103,99,
    17,18,24,47,99,99,99,99,  18,21,26,66,99,99,99,99,
    24,26,56,99,99,99,99,99,  47,66,99,99,99,99,99,99,
    99,99,99,99,99,99,99,99,  99,99,99,99,99,99,99,99,
    99,99,99,99,99,99,99,99,  99,99,99,99,99,99,99,99 };
__constant__ float cRQf[128] = {
    1.f/16,1.f/11,1.f/10,1.f/16,1.f/24,1.f/40,1.f/51,1.f/61,
    1.f/12,1.f/12,1.f/14,1.f/19,1.f/26,1.f/58,1.f/60,1.f/55,
    1.f/14,1.f/13,1.f/16,1.f/24,1.f/40,1.f/57,1.f/69,1.f/56,
    1.f/14,1.f/17,1.f/22,1.f/29,1.f/51,1.f/87,1.f/80,1.f/62,
    1.f/18,1.f/22,1.f/37,1.f/56,1.f/68,1.f/109,1.f/103,1.f/77,
    1.f/24,1.f/35,1.f/55,1.f/64,1.f/81,1.f/104,1.f/113,1.f/92,
    1.f/49,1.f/64,1.f/78,1.f/87,1.f/103,1.f/121,1.f/120,1.f/101,
    1.f/72,1.f/92,1.f/95,1.f/98,1.f/112,1.f/100,1.f/103,1.f/99,
    1.f/17,1.f/18,1.f/24,1.f/47,1.f/99,1.f/99,1.f/99,1.f/99,
    1.f/18,1.f/21,1.f/26,1.f/66,1.f/99,1.f/99,1.f/99,1.f/99,
    1.f/24,1.f/26,1.f/56,1.f/99,1.f/99,1.f/99,1.f/99,1.f/99,
    1.f/47,1.f/66,1.f/99,1.f/99,1.f/99,1.f/99,1.f/99,1.f/99,
    1.f/99,1.f/99,1.f/99,1.f/99,1.f/99,1.f/99,1.f/99,1.f/99,
    1.f/99,1.f/99,1.f/99,1.f/99,1.f/99,1.f/99,1.f/99,1.f/99,
    1.f/99,1.f/99,1.f/99,1.f/99,1.f/99,1.f/99,1.f/99,1.f/99,
    1.f/99,1.f/99,1.f/99,1.f/99,1.f/99,1.f/99,1.f/99,1.f/99 };

#define NC_A0 0.0158730159f
#define NC_B0 (-1.93476190e-8f)
#define NC_C0 0.0222539619f
#define NC_K0 (-4.8373935f)
#define NC_A1 0.0161030596f
#define NC_B1 (-0.0055416377f)
#define NC_C1 (-0.0114997768f)
#define NC_K1 0.2006247f
#define NC_A2 0.0149925037f
#define NC_B2 0.0265667181f
#define NC_C2 6.09145427e-9f
#define NC_K2 (-5.1081869f)

typedef unsigned long long ull;

__device__ __forceinline__ ull pk(float lo, float hi) {
    float2 t = make_float2(lo, hi); ull r; memcpy(&r, &t, 8); return r;
}
__device__ __forceinline__ ull pk1(float x) { return pk(x, x); }
__device__ __forceinline__ float2 unpk(ull a) {
    float2 t; memcpy(&t, &a, 8); return t;
}
__device__ __forceinline__ ull padd(ull a, ull b) {
    ull r; asm("add.rn.f32x2 %0,%1,%2;" : "=l"(r) : "l"(a), "l"(b)); return r;
}
__device__ __forceinline__ ull pmul(ull a, ull b) {
    ull r; asm("mul.rn.f32x2 %0,%1,%2;" : "=l"(r) : "l"(a), "l"(b)); return r;
}
__device__ __forceinline__ ull pfma(ull a, ull b, ull c) {
    ull r; asm("fma.rn.f32x2 %0,%1,%2,%3;" : "=l"(r) : "l"(a), "l"(b), "l"(c)); return r;
}
__device__ __forceinline__ ull psub(ull a, ull b) { return pfma(b, pk1(-1.0f), a); }

__device__ __forceinline__ void fdct8(float v[8]) {
    float e0=v[0]+v[7], e1=v[1]+v[6], e2=v[2]+v[5], e3=v[3]+v[4];
    float o0=v[0]-v[7], o1=v[1]-v[6], o2=v[2]-v[5], o3=v[3]-v[4];
    float s03=e0+e3, s12=e1+e2, d03=e0-e3, d12=e1-e2;
    v[0]=C4*(s03+s12);
    v[4]=C4*(s03-s12);
    v[2]=fmaf(C2,d03, C6*d12);
    v[6]=fmaf(C6,d03,-C2*d12);
    v[1]=fmaf(C1,o0,fmaf( C3,o1,fmaf( C5,o2, C7*o3)));
    v[3]=fmaf(C3,o0,fmaf(-C7,o1,fmaf(-C1,o2,-C5*o3)));
    v[5]=fmaf(C5,o0,fmaf(-C1,o1,fmaf( C7,o2, C3*o3)));
    v[7]=fmaf(C7,o0,fmaf(-C5,o1,fmaf( C3,o2,-C1*o3)));
}
__device__ __forceinline__ void idct8(float v[8]) {
    float sp=C4*(v[0]+v[4]), sm=C4*(v[0]-v[4]);
    float t1=fmaf(C2,v[2], C6*v[6]);
    float t2=fmaf(C6,v[2],-C2*v[6]);
    float E0=sp+t1, E1=sm+t2, E2=sm-t2, E3=sp-t1;
    float O0=fmaf(C1,v[1],fmaf( C3,v[3],fmaf( C5,v[5], C7*v[7])));
    float O1=fmaf(C3,v[1],fmaf(-C7,v[3],fmaf(-C1,v[5],-C5*v[7])));
    float O2=fmaf(C5,v[1],fmaf(-C1,v[3],fmaf( C7,v[5], C3*v[7])));
    float O3=fmaf(C7,v[1],fmaf(-C5,v[3],fmaf( C3,v[5],-C1*v[7])));
    v[0]=E0+O0; v[7]=E0-O0;
    v[1]=E1+O1; v[6]=E1-O1;
    v[2]=E2+O2; v[5]=E2-O2;
    v[3]=E3+O3; v[4]=E3-O3;
}
__device__ __forceinline__ void fdct8p(ull v[8]) {
    ull e0=padd(v[0],v[7]), e1=padd(v[1],v[6]), e2=padd(v[2],v[5]), e3=padd(v[3],v[4]);
    ull o0=psub(v[0],v[7]), o1=psub(v[1],v[6]), o2=psub(v[2],v[5]), o3=psub(v[3],v[4]);
    ull s03=padd(e0,e3), s12=padd(e1,e2), d03=psub(e0,e3), d12=psub(e1,e2);
    v[0]=pmul(pk1(C4), padd(s03,s12));
    v[4]=pmul(pk1(C4), psub(s03,s12));
    v[2]=pfma(pk1(C2),d03, pmul(pk1( C6),d12));
    v[6]=pfma(pk1(C6),d03, pmul(pk1(-C2),d12));
    v[1]=pfma(pk1(C1),o0, pfma(pk1( C3),o1, pfma(pk1( C5),o2, pmul(pk1( C7),o3))));
    v[3]=pfma(pk1(C3),o0, pfma(pk1(-C7),o1, pfma(pk1(-C1),o2, pmul(pk1(-C5),o3))));
    v[5]=pfma(pk1(C5),o0, pfma(pk1(-C1),o1, pfma(pk1( C7),o2, pmul(pk1( C3),o3))));
    v[7]=pfma(pk1(C7),o0, pfma(pk1(-C5),o1, pfma(pk1( C3),o2, pmul(pk1(-C1),o3))));
}
__device__ __forceinline__ void idct8p(ull v[8]) {
    ull sp=pmul(pk1(C4), padd(v[0],v[4]));
    ull sm=pmul(pk1(C4), psub(v[0],v[4]));
    ull t1=pfma(pk1(C2),v[2], pmul(pk1( C6),v[6]));
    ull t2=pfma(pk1(C6),v[2], pmul(pk1(-C2),v[6]));
    ull E0=padd(sp,t1), E1=padd(sm,t2), E2=psub(sm,t2), E3=psub(sp,t1);
    ull O0=pfma(pk1(C1),v[1], pfma(pk1( C3),v[3], pfma(pk1( C5),v[5], pmul(pk1( C7),v[7]))));
    ull O1=pfma(pk1(C3),v[1], pfma(pk1(-C7),v[3], pfma(pk1(-C1),v[5], pmul(pk1(-C5),v[7]))));
    ull O2=pfma(pk1(C5),v[1], pfma(pk1(-C1),v[3], pfma(pk1( C7),v[5], pmul(pk1( C3),v[7]))));
    ull O3=pfma(pk1(C7),v[1], pfma(pk1(-C5),v[3], pfma(pk1( C3),v[5], pmul(pk1(-C1),v[7]))));
    v[0]=padd(E0,O0); v[7]=psub(E0,O0);
    v[1]=padd(E1,O1); v[6]=psub(E1,O1);
    v[2]=padd(E2,O2); v[5]=psub(E2,O2);
    v[3]=padd(E3,O3); v[4]=psub(E3,O3);
}

// ---- Y transpose across 8 lanes via xor-butterfly shuffles (proven in R3) ----
// lane holds row r (= lane>>2); partner mask m<<2 keeps group (lane&3)
__device__ __forceinline__ void xposeShfl(float v[8], int r) {
    #pragma unroll
    for (int m = 1; m < 8; m <<= 1) {
        bool up = (r & m) != 0;
        #pragma unroll
        for (int c0 = 0; c0 < 8; ++c0) {
            if (c0 & m) continue;
            int c1 = c0 | m;
            float send = up ? v[c0] : v[c1];
            float got = __shfl_xor_sync(0xffffffffu, send, m << 2);
            if (up) v[c0] = got; else v[c1] = got;
        }
    }
}

// ---- UV smem transpose (conflict-free, validated R8-R13) ----
#define RPU 10
#define GPU 84

__device__ __forceinline__ void writeUV(const ull uv[8], ull* uvbg, int r) {
    ull* uw = uvbg + RPU * r;
    #pragma unroll
    for (int k = 0; k < 8; k += 2)
        *(ulonglong2*)(uw + k) = make_ulonglong2(uv[k], uv[k+1]);
}
__device__ __forceinline__ void readUV(ull uv[8], const ull* uvbg, int r) {
    #pragma unroll
    for (int k = 0; k < 8; ++k) uv[k] = uvbg[RPU * k + r];
}

__global__ __launch_bounds__(256, 4)
void jpeg_roundtrip_kernel(const float* __restrict__ in, float* __restrict__ out)
{
    __shared__ __align__(16) ull  uvb[8 * 4 * GPU];   // 21504 B
    __shared__ float qt[256];

    const int tid  = threadIdx.x;
    const int warp = tid >> 5;
    const int lane = tid & 31;
    const int r    = lane >> 2;
    const int g    = lane & 3;

    {   // build interleaved quant table
        int w  = tid & 1, rr = (tid >> 1) & 7, ii = (tid >> 4) & 7, ch = tid >> 7;
        int si = ch * 64 + ii * 8 + rr;
        qt[tid] = w ? cRQf[si] : cQf[si];
    }

    ull* uvbg = uvb + (warp * 4 + g) * GPU;

    const int x0   = blockIdx.x * 256 + (warp * 4 + g) * 8;
    const int y    = blockIdx.y * 8 + r;
    const int base = y * IMG_W + x0;

    float vY[8];
    ull   pUV[8];

    // ---- load RGB + forward color ----
    {
        const float4 Ra = *(const float4*)(in + base);
        const float4 Rb = *(const float4*)(in + base + 4);
        const float4 Ga = *(const float4*)(in + base + PLANE);
        const float4 Gb = *(const float4*)(in + base + PLANE + 4);
        const float4 Ba = *(const float4*)(in + base + 2*PLANE);
        const float4 Bb = *(const float4*)(in + base + 2*PLANE + 4);

        __syncthreads();   // quant table ready

        float R[8] = {Ra.x,Ra.y,Ra.z,Ra.w, Rb.x,Rb.y,Rb.z,Rb.w};
        float G[8] = {Ga.x,Ga.y,Ga.z,Ga.w, Gb.x,Gb.y,Gb.z,Gb.w};
        float B[8] = {Ba.x,Ba.y,Ba.z,Ba.w, Bb.x,Bb.y,Bb.z,Bb.w};
        #pragma unroll
        for (int k = 0; k < 8; ++k) {
            vY[k] = 0.299f*R[k] + 0.587f*G[k] + 0.114f*B[k];
            float u = fmaf(-0.168736f, R[k], fmaf(-0.331264f, G[k], fmaf(0.5f, B[k], 128.0f)));
            float v = fmaf(0.5f, R[k], fmaf(-0.418688f, G[k], fmaf(-0.081312f, B[k], 128.0f)));
            pUV[k] = pk(u, v);
        }
    }

    // ---- stage 1: row DCT; Y transposes on SHFL pipe, UV on smem ----
    fdct8p(pUV); writeUV(pUV, uvbg, r);     // UV stores in flight...
    fdct8(vY);   xposeShfl(vY, r);          // ...while Y shuffles
    __syncwarp();
    readUV(pUV, uvbg, r);
    __syncwarp();

    // ---- stage 2: column DCT + quant + column IDCT ----
    fdct8p(pUV);
    fdct8(vY);
    #pragma unroll
    for (int i = 0; i < 8; ++i) {
        float2 qy = *(const float2*)(qt + i * 16 + r * 2);
        float2 qc = *(const float2*)(qt + 128 + i * 16 + r * 2);
        {   float sv = vY[i];
            float d  = sv * qy.y;
            float rn = rintf(d);
            float e  = fmaf(-rn, qy.x, sv) * qy.y;
            vY[i]    = fmaf(e*e, e, rn) * qy.x; }
        {   float2 s = unpk(pUV[i]);
            float d0 = s.x * qc.y, d1 = s.y * qc.y;
            float r0 = rintf(d0), r1 = rintf(d1);
            float e0 = fmaf(-r0, qc.x, s.x) * qc.y;
            float e1 = fmaf(-r1, qc.x, s.y) * qc.y;
            pUV[i] = pk(fmaf(e0*e0, e0, r0) * qc.x,
                        fmaf(e1*e1, e1, r1) * qc.x); }
    }
    idct8p(pUV); writeUV(pUV, uvbg, r);
    idct8(vY);   xposeShfl(vY, r);
    __syncwarp();
    readUV(pUV, uvbg, r);

    // ---- stage 4: row IDCT ----
    idct8(vY);
    idct8p(pUV);

    // ---- folded inverse color + normalize + store ----
    #pragma unroll
    for (int h = 0; h < 2; ++h) {
        float4 Ro, Go, Bo;
        #pragma unroll
        for (int k = 0; k < 4; ++k) {
            int c = h*4 + k;
            float yv = vY[c];
            float2 uvv = unpk(pUV[c]);
            float u = uvv.x, v = uvv.y;
            ((float*)&Ro)[k] = fmaf(yv, NC_A0, fmaf(u, NC_B0, fmaf(v, NC_C0, NC_K0)));
            ((float*)&Go)[k] = fmaf(yv, NC_A1, fmaf(u, NC_B1, fmaf(v, NC_C1, NC_K1)));
            ((float*)&Bo)[k] = fmaf(yv, NC_A2, fmaf(u, NC_B2, fmaf(v, NC_C2, NC_K2)));
        }
        *(float4*)(out + base + h*4)           = Ro;
        *(float4*)(out + base + PLANE + h*4)   = Go;
        *(float4*)(out + base + 2*PLANE + h*4) = Bo;
    }
}

extern "C" void kernel_launch(void* const* d_in, const int* in_sizes, int n_in,
                              void* d_out, int out_size)
{
    const float* in = (const float*)d_in[0];
    float* out = (float*)d_out;
    dim3 grid(IMG_W / 256, IMG_H / 8);
    jpeg_roundtrip_kernel<<<grid, 256>>>(in, out);
}